// round 1
// baseline (speedup 1.0000x reference)
#include <cuda_runtime.h>
#include <math.h>

#define B_   64
#define S_   4096
#define DEC_ 512
#define ENC_ 256

// Scratch (allocation-free rule: __device__ globals)
__device__ float g_dpe[B_ * ENC_];      // decoder_proj + bd + be, per batch
__device__ float g_scores[B_ * S_];     // pre-softmax scores

// ---------------------------------------------------------------------------
// Kernel 1: dpe[b,f] = sum_d dh[b,d]*Wd[d,f] + bd[f] + be[f]
// ---------------------------------------------------------------------------
__global__ void k_decproj(const float* __restrict__ dh, const float* __restrict__ Wd,
                          const float* __restrict__ bd, const float* __restrict__ be) {
    int b = blockIdx.x;
    int f = threadIdx.x;                 // 256 threads
    __shared__ float sdh[DEC_];
    for (int d = f; d < DEC_; d += ENC_) sdh[d] = dh[b * DEC_ + d];
    __syncthreads();
    float acc = bd[f] + be[f];
#pragma unroll 8
    for (int d = 0; d < DEC_; ++d) acc += sdh[d] * Wd[d * ENC_ + f];
    g_dpe[b * ENC_ + f] = acc;
}

// ---------------------------------------------------------------------------
// Kernel 2: fused GEMM + tanh + Wa-dot -> scores
//   CTA tile: 128 rows (one batch slice) x 256 cols (all ENC), BK=8
//   256 threads = 16x16; thread micro-tile 8 rows x 8 col-pairs (f32x2)
// ---------------------------------------------------------------------------
__device__ __forceinline__ void cp16(void* dst, const void* src) {
    unsigned d = (unsigned)__cvta_generic_to_shared(dst);
    asm volatile("cp.async.cg.shared.global [%0], [%1], 16;\n" :: "r"(d), "l"(src));
}
#define CP_COMMIT() asm volatile("cp.async.commit_group;\n" ::: "memory")
#define CP_WAIT1()  asm volatile("cp.async.wait_group 1;\n" ::: "memory")

__global__ __launch_bounds__(256, 1)
void k_scores(const float* __restrict__ enc, const float* __restrict__ We,
              const float* __restrict__ Wa) {
    __shared__ __align__(16) float As[2][128][8];     // 8 KB
    __shared__ __align__(16) float Bs[2][8][256];     // 16 KB
    __shared__ float red[128][17];                    // 8.5 KB, padded
    __shared__ float sdpe[256];
    __shared__ float swa[256];

    const int tid = threadIdx.x;
    const int tx = tid & 15, ty = tid >> 4;
    const int row0 = blockIdx.x * 128;                // global (b*S + s) row
    const int b = row0 >> 12;                         // S = 4096 rows per batch

    sdpe[tid] = g_dpe[b * 256 + tid];
    swa[tid]  = Wa[tid];

    // A-tile loader mapping: 1 float4 per thread per K-tile
    const int arow = tid >> 1, aseg = (tid & 1) * 4;
    const float* agp = enc + (size_t)(row0 + arow) * 256 + aseg;

    unsigned long long acc[8][8];
#pragma unroll
    for (int i = 0; i < 8; ++i)
#pragma unroll
        for (int j = 0; j < 8; ++j) acc[i][j] = 0ull;

    // prologue: K-tile 0
    {
        cp16(&As[0][arow][aseg], agp);
        int i0 = tid, i1 = tid + 256;
        cp16(&Bs[0][i0 >> 6][(i0 & 63) * 4], We + (i0 >> 6) * 256 + (i0 & 63) * 4);
        cp16(&Bs[0][i1 >> 6][(i1 & 63) * 4], We + (i1 >> 6) * 256 + (i1 & 63) * 4);
        CP_COMMIT();
    }

    for (int t = 0; t < 32; ++t) {
        const int buf = t & 1;
        if (t + 1 < 32) {                              // prefetch next K-tile
            const int kt = (t + 1) * 8, nb = buf ^ 1;
            cp16(&As[nb][arow][aseg], agp + kt);
            int i0 = tid, i1 = tid + 256;
            int kr0 = i0 >> 6, c0 = (i0 & 63) * 4;
            int kr1 = i1 >> 6, c1 = (i1 & 63) * 4;
            cp16(&Bs[nb][kr0][c0], We + (kt + kr0) * 256 + c0);
            cp16(&Bs[nb][kr1][c1], We + (kt + kr1) * 256 + c1);
        }
        CP_COMMIT();
        CP_WAIT1();                                    // tile t resident
        __syncthreads();

#pragma unroll
        for (int k = 0; k < 8; ++k) {
            unsigned long long ap[8], bp[8];
#pragma unroll
            for (int i = 0; i < 8; ++i) {
                float av = As[buf][ty * 8 + i][k];     // 2 addrs/warp -> broadcast
                asm("mov.b64 %0, {%1, %1};" : "=l"(ap[i]) : "f"(av));
            }
#pragma unroll
            for (int j = 0; j < 8; ++j)                // cols 2*tx + 32*j: conflict-free
                bp[j] = *(const unsigned long long*)&Bs[buf][k][2 * tx + 32 * j];
#pragma unroll
            for (int i = 0; i < 8; ++i)
#pragma unroll
                for (int j = 0; j < 8; ++j)
                    asm("fma.rn.f32x2 %0, %1, %2, %0;"
                        : "+l"(acc[i][j]) : "l"(ap[i]), "l"(bp[j]));
        }
        __syncthreads();                               // protect buf reuse at t+2
    }

    // Epilogue: scores partials = sum_f Wa[f] * tanh(dpe[f] + ep)
#pragma unroll
    for (int i = 0; i < 8; ++i) {
        float si = 0.f;
#pragma unroll
        for (int j = 0; j < 8; ++j) {
            float lo, hi;
            asm("mov.b64 {%0, %1}, %2;" : "=f"(lo), "=f"(hi) : "l"(acc[i][j]));
            const int c = 2 * tx + 32 * j;
            si += swa[c]     * tanhf(sdpe[c]     + lo);
            si += swa[c + 1] * tanhf(sdpe[c + 1] + hi);
        }
        red[ty * 8 + i][tx] = si;
    }
    __syncthreads();
    if (tid < 128) {
        float s = 0.f;
#pragma unroll
        for (int x = 0; x < 16; ++x) s += red[tid][x];
        g_scores[row0 + tid] = s;
    }
}

// ---------------------------------------------------------------------------
// Kernel 3: masked softmax over S per batch -> attn (output region)
// ---------------------------------------------------------------------------
__global__ void k_softmax(const int* __restrict__ mask, float* __restrict__ attn) {
    const int b = blockIdx.x, t = threadIdx.x;         // 1024 threads
    const float* sc = g_scores + b * S_;
    const int*   mk = mask + b * S_;
    float v[4], mx = -INFINITY;
#pragma unroll
    for (int i = 0; i < 4; ++i) {
        int s = t + i * 1024;
        float x = sc[s];
        if (mk[s] == 0) x = -1e10f;
        v[i] = x;
        mx = fmaxf(mx, x);
    }
    __shared__ float rb[32];
    for (int o = 16; o; o >>= 1) mx = fmaxf(mx, __shfl_xor_sync(~0u, mx, o));
    if ((t & 31) == 0) rb[t >> 5] = mx;
    __syncthreads();
    if (t < 32) {
        float m2 = rb[t];
        for (int o = 16; o; o >>= 1) m2 = fmaxf(m2, __shfl_xor_sync(~0u, m2, o));
        rb[t] = m2;
    }
    __syncthreads();
    mx = rb[0];
    __syncthreads();
    float e[4], tot = 0.f;
#pragma unroll
    for (int i = 0; i < 4; ++i) { e[i] = expf(v[i] - mx); tot += e[i]; }
    for (int o = 16; o; o >>= 1) tot += __shfl_xor_sync(~0u, tot, o);
    if ((t & 31) == 0) rb[t >> 5] = tot;
    __syncthreads();
    if (t < 32) {
        float s2 = rb[t];
        for (int o = 16; o; o >>= 1) s2 += __shfl_xor_sync(~0u, s2, o);
        rb[t] = s2;
    }
    __syncthreads();
    const float inv = 1.f / rb[0];
#pragma unroll
    for (int i = 0; i < 4; ++i) attn[b * S_ + t + i * 1024] = e[i] * inv;
}

// ---------------------------------------------------------------------------
// Kernel 4: context[b,e] = sum_s attn[b,s] * enc[b,s,e]  (float4 vectorized)
// ---------------------------------------------------------------------------
__global__ void k_context(const float* __restrict__ enc, const float* __restrict__ attn,
                          float* __restrict__ ctx) {
    const int b = blockIdx.x, t = threadIdx.x;         // 1024 threads
    const int c4 = t & 63, sg = t >> 6;                // 64 float4 cols x 16 s-phases
    const float4* e4 = (const float4*)enc + (size_t)b * S_ * 64;
    const float* at = attn + b * S_;
    float4 acc = make_float4(0.f, 0.f, 0.f, 0.f);
#pragma unroll 4
    for (int s = sg; s < S_; s += 16) {
        float a = at[s];
        float4 e = e4[(size_t)s * 64 + c4];
        acc.x += a * e.x; acc.y += a * e.y; acc.z += a * e.z; acc.w += a * e.w;
    }
    __shared__ float4 sr[16][64];                      // 16 KB
    sr[sg][c4] = acc;
    __syncthreads();
    if (t < 64) {
        float4 r = sr[0][t];
#pragma unroll
        for (int g = 1; g < 16; ++g) {
            float4 q = sr[g][t];
            r.x += q.x; r.y += q.y; r.z += q.z; r.w += q.w;
        }
        ((float4*)ctx)[b * 64 + t] = r;
    }
}

// ---------------------------------------------------------------------------
// Launch
// ---------------------------------------------------------------------------
extern "C" void kernel_launch(void* const* d_in, const int* in_sizes, int n_in,
                              void* d_out, int out_size) {
    const float* dh   = (const float*)d_in[0];  // decoder_hidden [64,1,512]
    const float* enc  = (const float*)d_in[1];  // encoder_outputs [64,4096,256]
    const int*   mask = (const int*)  d_in[2];  // [64,4096]
    const float* Wd   = (const float*)d_in[3];  // [512,256]
    const float* bd   = (const float*)d_in[4];  // [256]
    const float* We   = (const float*)d_in[5];  // [256,256]
    const float* be   = (const float*)d_in[6];  // [256]
    const float* Wa   = (const float*)d_in[7];  // [256]
    // d_in[8] = ba: uniform additive shift on scores -> cancels in softmax.

    float* out  = (float*)d_out;
    float* ctx  = out;                 // context [64,1,256] first (return order)
    float* attn = out + B_ * ENC_;     // attn [64,4096] second

    k_decproj<<<B_, ENC_>>>(dh, Wd, bd, be);
    k_scores<<<(B_ * S_) / 128, 256>>>(enc, We, Wa);
    k_softmax<<<B_, 1024>>>(mask, attn);
    k_context<<<B_, 1024>>>(enc, attn, ctx);
}